// round 11
// baseline (speedup 1.0000x reference)
#include <cuda_runtime.h>
#include <cuda_bf16.h>

// Sbert idf-weighted masked mean pooling — row skipping + pipelined metadata.
// hidden [B, L, D] f32, ids [B, L] i32, mask [B, L] i32, idf [V] f32
// out[b,d] = sum_l hidden[b,l,d] * (mask[b,l] ? idf[ids[b,l]] : 0) / max(sum_l mask[b,l], 1e-9)
//
// ~50% of tokens have weight exactly 0 (mask==0); their rows are never loaded
// (fmaf(h,0,acc)==acc bit-exactly). Compacted (idx, w) metadata is consumed as
// int4/float4 groups, prefetched one group ahead into registers so the smem
// reads hide under the in-flight global loads (keeps DRAM demand saturated).

constexpr int L = 100;
constexpr int D = 768;
constexpr int D4 = D / 4;        // 192 float4 lanes per row
constexpr int THREADS = D4;

__global__ __launch_bounds__(THREADS) void sbert_pool_kernel(
    const float* __restrict__ hidden,
    const int*   __restrict__ ids,
    const int*   __restrict__ mask,
    const float* __restrict__ idf,
    float*       __restrict__ out)
{
    __shared__ float w[L];                         // dense per-token weight
    __shared__ __align__(16) float wc[L + 4];      // compacted weights
    __shared__ __align__(16) int   idx[L + 4];     // compacted token indices

    const int b = blockIdx.x;
    const int t = threadIdx.x;

    // ── Phase A: gather weights; denominator = mask count ──
    int m = 0;
    float wv = 0.0f;
    if (t < L) {
        const int base = b * L + t;
        m = mask[base];
        if (m) wv = idf[ids[base]];
        w[t] = wv;
    }
    const int cnt = __syncthreads_count(m != 0);           // barrier #1
    const float inv = 1.0f / fmaxf((float)cnt, 1e-9f);

    // ── Phase A2: order-preserving compaction (deterministic, no atomics) ──
    if (t < L && wv != 0.0f) {
        int pos = 0;
        #pragma unroll 4
        for (int j = 0; j < t; ++j) pos += (w[j] != 0.0f);
        idx[pos] = t;
        wc[pos]  = wv;
    }
    const int nnz = __syncthreads_count(t < L && wv != 0.0f);  // barrier #2

    // ── Phase B: stream the nnz useful rows, metadata pipelined in registers ──
    const float4* __restrict__ hp =
        reinterpret_cast<const float4*>(hidden + (size_t)b * L * D) + t;

    float4 acc = make_float4(0.f, 0.f, 0.f, 0.f);
    const int n4 = nnz & ~3;

    if (n4 > 0) {
        int4   I = *reinterpret_cast<const int4*>(idx);
        float4 W = *reinterpret_cast<const float4*>(wc);
        int j = 0;
        for (;;) {
            // 4 independent LDG.128 issue immediately from register addresses
            const float4 h0 = hp[(size_t)I.x * D4];
            const float4 h1 = hp[(size_t)I.y * D4];
            const float4 h2 = hp[(size_t)I.z * D4];
            const float4 h3 = hp[(size_t)I.w * D4];

            // prefetch next group's metadata while globals are in flight
            j += 4;
            const bool more = (j < n4);
            int4 In; float4 Wn;
            if (more) {
                In = *reinterpret_cast<const int4*>(idx + j);
                Wn = *reinterpret_cast<const float4*>(wc + j);
            }

            // strict ascending order -> accumulation identical to dense loop
            acc.x = fmaf(h0.x, W.x, acc.x);
            acc.y = fmaf(h0.y, W.x, acc.y);
            acc.z = fmaf(h0.z, W.x, acc.z);
            acc.w = fmaf(h0.w, W.x, acc.w);
            acc.x = fmaf(h1.x, W.y, acc.x);
            acc.y = fmaf(h1.y, W.y, acc.y);
            acc.z = fmaf(h1.z, W.y, acc.z);
            acc.w = fmaf(h1.w, W.y, acc.w);
            acc.x = fmaf(h2.x, W.z, acc.x);
            acc.y = fmaf(h2.y, W.z, acc.y);
            acc.z = fmaf(h2.z, W.z, acc.z);
            acc.w = fmaf(h2.w, W.z, acc.w);
            acc.x = fmaf(h3.x, W.w, acc.x);
            acc.y = fmaf(h3.y, W.w, acc.y);
            acc.z = fmaf(h3.z, W.w, acc.z);
            acc.w = fmaf(h3.w, W.w, acc.w);

            if (!more) break;
            I = In; W = Wn;
        }
    }

    // remainder (<=3 rows)
    for (int j = n4; j < nnz; ++j) {
        const float4 h = hp[(size_t)idx[j] * D4];
        const float wj = wc[j];
        acc.x = fmaf(h.x, wj, acc.x);
        acc.y = fmaf(h.y, wj, acc.y);
        acc.z = fmaf(h.z, wj, acc.z);
        acc.w = fmaf(h.w, wj, acc.w);
    }

    acc.x *= inv; acc.y *= inv; acc.z *= inv; acc.w *= inv;
    reinterpret_cast<float4*>(out + (size_t)b * D)[t] = acc;
}

extern "C" void kernel_launch(void* const* d_in, const int* in_sizes, int n_in,
                              void* d_out, int out_size) {
    const float* hidden = (const float*)d_in[0];
    const int*   ids    = (const int*)  d_in[1];
    const int*   mask   = (const int*)  d_in[2];
    const float* idf    = (const float*)d_in[3];
    float*       out    = (float*)d_out;

    const int B = out_size / D;   // 4096
    sbert_pool_kernel<<<B, THREADS>>>(hidden, ids, mask, idf, out);
}

// round 12
// speedup vs baseline: 1.1436x; 1.1436x over previous
#include <cuda_runtime.h>
#include <cuda_bf16.h>
#include <stdint.h>

// Sbert idf-weighted masked mean pooling — split metadata/stream kernels.
// hidden [B, L, D] f32, ids [B, L] i32, mask [B, L] i32, idf [V] f32
// out[b,d] = sum_l hidden[b,l,d] * (mask[b,l] ? idf[ids[b,l]] : 0) / max(sum_l mask[b,l], 1e-9)
//
// ~50% of tokens have weight exactly 0 -> their 3KB hidden rows are never read
// (fmaf(h,0,acc)==acc bit-exactly). Kernel 1 precomputes, per batch row, the
// order-preserving compacted (token idx, weight) list + nnz + 1/cnt into global
// scratch. Kernel 2 (the streamer) then starts each CTA with ONE parallel
// metadata load burst + one barrier — no dependent gather chain, no smem scan —
// keeping the DRAM pipe fed.

constexpr int L  = 100;
constexpr int D  = 768;
constexpr int D4 = D / 4;          // 192 float4 lanes per row
constexpr int THREADS = D4;
constexpr int MAXB = 4096;
constexpr int MSTRIDE = 104;       // padded metadata row stride

// ── global scratch (static __device__ arrays: allowed) ──
__device__ float   g_wc [MAXB * MSTRIDE];
__device__ uint8_t g_idx[MAXB * MSTRIDE];
__device__ int     g_nnz[MAXB];
__device__ float   g_inv[MAXB];

// ── Kernel 1: one warp per batch row; ballot-based order-preserving compaction ──
constexpr int K1_WARPS = 8;
__global__ __launch_bounds__(K1_WARPS * 32) void sbert_meta_kernel(
    const int*   __restrict__ ids,
    const int*   __restrict__ mask,
    const float* __restrict__ idf,
    int B)
{
    const int lane = threadIdx.x & 31;
    const int b = blockIdx.x * K1_WARPS + (threadIdx.x >> 5);
    if (b >= B) return;

    int cnt = 0;     // mask count (denominator)
    int base = 0;    // compacted write cursor
    #pragma unroll
    for (int c = 0; c < 4; ++c) {
        const int tk = c * 32 + lane;
        const bool valid = (tk < L);
        int m = 0;
        float wv = 0.0f;
        if (valid) {
            const int g = b * L + tk;
            m = mask[g];
            if (m) wv = idf[ids[g]];
        }
        cnt += __popc(__ballot_sync(0xFFFFFFFFu, m != 0));
        const unsigned nzb = __ballot_sync(0xFFFFFFFFu, wv != 0.0f);
        if (wv != 0.0f) {
            const int pos = base + __popc(nzb & ((1u << lane) - 1u));
            g_wc [b * MSTRIDE + pos] = wv;
            g_idx[b * MSTRIDE + pos] = (uint8_t)tk;
        }
        base += __popc(nzb);
    }
    if (lane == 0) {
        g_nnz[b] = base;
        g_inv[b] = 1.0f / fmaxf((float)cnt, 1e-9f);
    }
}

// ── Kernel 2: pure streamer. One flat metadata load burst, then the loop. ──
__global__ __launch_bounds__(THREADS) void sbert_pool_kernel(
    const float* __restrict__ hidden,
    float*       __restrict__ out)
{
    __shared__ float wcs[MSTRIDE];
    __shared__ int   idxs[MSTRIDE];

    const int b = blockIdx.x;
    const int t = threadIdx.x;

    // all loads independent -> single memory round trip, then one barrier
    const int   nnz = g_nnz[b];        // broadcast
    const float inv = g_inv[b];        // broadcast
    if (t < MSTRIDE) {
        wcs[t]  = g_wc [b * MSTRIDE + t];
        idxs[t] = (int)g_idx[b * MSTRIDE + t];
    }
    __syncthreads();

    const float4* __restrict__ hp =
        reinterpret_cast<const float4*>(hidden + (size_t)b * L * D) + t;

    float4 acc = make_float4(0.f, 0.f, 0.f, 0.f);
    #pragma unroll 4
    for (int j = 0; j < nnz; ++j) {
        const float4 h = hp[(size_t)idxs[j] * D4];
        const float wj = wcs[j];
        acc.x = fmaf(h.x, wj, acc.x);
        acc.y = fmaf(h.y, wj, acc.y);
        acc.z = fmaf(h.z, wj, acc.z);
        acc.w = fmaf(h.w, wj, acc.w);
    }

    acc.x *= inv; acc.y *= inv; acc.z *= inv; acc.w *= inv;
    reinterpret_cast<float4*>(out + (size_t)b * D)[t] = acc;
}

extern "C" void kernel_launch(void* const* d_in, const int* in_sizes, int n_in,
                              void* d_out, int out_size) {
    const float* hidden = (const float*)d_in[0];
    const int*   ids    = (const int*)  d_in[1];
    const int*   mask   = (const int*)  d_in[2];
    const float* idf    = (const float*)d_in[3];
    float*       out    = (float*)d_out;

    const int B = out_size / D;   // 4096
    const int g1 = (B + K1_WARPS - 1) / K1_WARPS;
    sbert_meta_kernel<<<g1, K1_WARPS * 32>>>(ids, mask, idf, B);
    sbert_pool_kernel<<<B, THREADS>>>(hidden, out);
}

// round 14
// speedup vs baseline: 1.1607x; 1.0149x over previous
#include <cuda_runtime.h>
#include <cuda_bf16.h>
#include <stdint.h>

// Sbert idf-weighted masked mean pooling — split meta kernel + fine-grained streamer.
// hidden [B, L, D] f32, ids [B, L] i32, mask [B, L] i32, idf [V] f32
// out[b,d] = sum_l hidden[b,l,d] * (mask[b,l] ? idf[ids[b,l]] : 0) / max(sum_l mask[b,l], 1e-9)
//
// ~50% of tokens have weight exactly 0 -> their hidden rows are never read
// (fmaf(h,0,acc)==acc bit-exactly). Kernel 1 compacts (idx, w) per batch row.
// Kernel 2 streams with a 3x finer work quantum: CTA (b, part) = 64 threads
// covering 256 of the 768 columns, so per-CTA lifetime is ~1/3 and the
// end-of-grid drain tail (the dominant DRAM idle source) shrinks accordingly.
// Adjacent blockIdx = same row's contiguous column segments (page locality).

constexpr int L  = 100;
constexpr int D  = 768;
constexpr int D4 = D / 4;          // 192 float4 lanes per full row
constexpr int SPLIT = 3;           // column segments per row
constexpr int SEG4  = D4 / SPLIT;  // 64 float4 lanes per segment
constexpr int THREADS2 = SEG4;     // 64 threads per streamer CTA
constexpr int MAXB = 4096;
constexpr int MSTRIDE = 104;       // padded metadata row stride

// ── global scratch (static __device__ arrays: allowed) ──
__device__ float   g_wc [MAXB * MSTRIDE];
__device__ uint8_t g_idx[MAXB * MSTRIDE];
__device__ int     g_nnz[MAXB];
__device__ float   g_inv[MAXB];

// ── Kernel 1: one warp per batch row; ballot-based order-preserving compaction ──
constexpr int K1_WARPS = 8;
__global__ __launch_bounds__(K1_WARPS * 32) void sbert_meta_kernel(
    const int*   __restrict__ ids,
    const int*   __restrict__ mask,
    const float* __restrict__ idf,
    int B)
{
    const int lane = threadIdx.x & 31;
    const int b = blockIdx.x * K1_WARPS + (threadIdx.x >> 5);
    if (b >= B) return;

    int cnt = 0;     // mask count (denominator)
    int base = 0;    // compacted write cursor
    #pragma unroll
    for (int c = 0; c < 4; ++c) {
        const int tk = c * 32 + lane;
        const bool valid = (tk < L);
        int m = 0;
        float wv = 0.0f;
        if (valid) {
            const int g = b * L + tk;
            m = mask[g];
            if (m) wv = idf[ids[g]];
        }
        cnt += __popc(__ballot_sync(0xFFFFFFFFu, m != 0));
        const unsigned nzb = __ballot_sync(0xFFFFFFFFu, wv != 0.0f);
        if (wv != 0.0f) {
            const int pos = base + __popc(nzb & ((1u << lane) - 1u));
            g_wc [b * MSTRIDE + pos] = wv;
            g_idx[b * MSTRIDE + pos] = (uint8_t)tk;
        }
        base += __popc(nzb);
    }
    if (lane == 0) {
        g_nnz[b] = base;
        g_inv[b] = 1.0f / fmaxf((float)cnt, 1e-9f);
    }
}

// ── Kernel 2: fine-grained streamer. CTA (b, part) covers 256 columns. ──
__global__ __launch_bounds__(THREADS2) void sbert_pool_kernel(
    const float* __restrict__ hidden,
    float*       __restrict__ out)
{
    __shared__ float wcs[MSTRIDE];
    __shared__ int   idxs[MSTRIDE];

    const int b    = blockIdx.x / SPLIT;
    const int part = blockIdx.x % SPLIT;
    const int t    = threadIdx.x;

    // flat metadata burst: independent loads, one barrier
    const int   nnz = g_nnz[b];
    const float inv = g_inv[b];
    {
        wcs[t]       = g_wc [b * MSTRIDE + t];
        idxs[t]      = (int)g_idx[b * MSTRIDE + t];
        const int t2 = t + THREADS2;
        if (t2 < MSTRIDE) {
            wcs[t2]  = g_wc [b * MSTRIDE + t2];
            idxs[t2] = (int)g_idx[b * MSTRIDE + t2];
        }
    }
    __syncthreads();

    const int lane4 = part * SEG4 + t;   // this thread's float4 column
    const float4* __restrict__ hp =
        reinterpret_cast<const float4*>(hidden + (size_t)b * L * D) + lane4;

    float4 acc = make_float4(0.f, 0.f, 0.f, 0.f);
    #pragma unroll 4
    for (int j = 0; j < nnz; ++j) {
        const float4 h = hp[(size_t)idxs[j] * D4];
        const float wj = wcs[j];
        acc.x = fmaf(h.x, wj, acc.x);
        acc.y = fmaf(h.y, wj, acc.y);
        acc.z = fmaf(h.z, wj, acc.z);
        acc.w = fmaf(h.w, wj, acc.w);
    }

    acc.x *= inv; acc.y *= inv; acc.z *= inv; acc.w *= inv;
    reinterpret_cast<float4*>(out + (size_t)b * D)[lane4] = acc;
}

extern "C" void kernel_launch(void* const* d_in, const int* in_sizes, int n_in,
                              void* d_out, int out_size) {
    const float* hidden = (const float*)d_in[0];
    const int*   ids    = (const int*)  d_in[1];
    const int*   mask   = (const int*)  d_in[2];
    const float* idf    = (const float*)d_in[3];
    float*       out    = (float*)d_out;

    const int B = out_size / D;   // 4096
    const int g1 = (B + K1_WARPS - 1) / K1_WARPS;
    sbert_meta_kernel<<<g1, K1_WARPS * 32>>>(ids, mask, idf, B);
    sbert_pool_kernel<<<B * SPLIT, THREADS2>>>(hidden, out);
}